// round 1
// baseline (speedup 1.0000x reference)
#include <cuda_runtime.h>
#include <cstdint>

#define BB 512
#define RR 264
#define KK 32
#define SS 9
#define RSTRIDE 36            // padded row stride in floats (144 B, 16B-aligned)
#define NSPLIT 4
#define ROWS_PER (RR / NSPLIT) // 66
#define NTHREADS 288

__device__ __constant__ int   c_ends[SS]  = {28, 58, 92, 121, 150, 180, 210, 240, 264};
__device__ __constant__ float c_sizes[SS] = {28.f, 30.f, 34.f, 29.f, 29.f, 30.f, 30.f, 30.f, 24.f};

__device__ __forceinline__ unsigned long long fma2(unsigned long long a,
                                                   unsigned long long b,
                                                   unsigned long long c) {
    unsigned long long d;
    asm("fma.rn.f32x2 %0, %1, %2, %3;" : "=l"(d) : "l"(a), "l"(b), "l"(c));
    return d;
}
__device__ __forceinline__ unsigned long long add2(unsigned long long a,
                                                   unsigned long long b) {
    unsigned long long d;
    asm("add.rn.f32x2 %0, %1, %2;" : "=l"(d) : "l"(a), "l"(b));
    return d;
}
__device__ __forceinline__ float sum2(unsigned long long a) {
    return __uint_as_float((unsigned)(a & 0xffffffffull)) +
           __uint_as_float((unsigned)(a >> 32));
}

extern "C" __global__ void __launch_bounds__(NTHREADS, 3)
gram_kernel(const float* __restrict__ E, float* __restrict__ out)
{
    float* intra = out;
    float* inter = out + (size_t)BB * RR * RR;
    float* adj   = inter + (size_t)BB * SS * SS;

    extern __shared__ float sE[];          // [RR][RSTRIDE]
    __shared__ int   sSeg[RR];
    __shared__ float sSum[SS * KK];

    const int b     = blockIdx.y;
    const int split = blockIdx.x;
    const int tid   = threadIdx.x;
    const float* Eb = E + (size_t)b * (RR * KK);

    // ---- cooperative load of E[b] into padded smem (float4 coalesced) ----
    for (int i = tid; i < (RR * KK) / 4; i += NTHREADS) {
        float4 v = reinterpret_cast<const float4*>(Eb)[i];
        int row = i >> 3, kq = i & 7;
        *reinterpret_cast<float4*>(&sE[row * RSTRIDE + kq * 4]) = v;
    }
    // ---- segment id per ROI ----
    for (int i = tid; i < RR; i += NTHREADS) {
        int s = 0;
        #pragma unroll
        for (int j = 0; j < SS; j++) s += (i >= c_ends[j]) ? 1 : 0;
        sSeg[i] = s;
    }
    __syncthreads();

    const int  c      = tid;
    const bool active = (c < RR);
    const int  cc     = active ? c : 0;

    // column vector of this thread, packed as 16 x f32x2
    unsigned long long bv[16];
    #pragma unroll
    for (int q = 0; q < 16; q++)
        bv[q] = *reinterpret_cast<const unsigned long long*>(&sE[cc * RSTRIDE + 2 * q]);
    const int segc = sSeg[cc];

    const int r0 = split * ROWS_PER;
    float* adjp   = adj   + (((size_t)b * RR + r0) * RR) + cc;
    float* intrap = intra + (((size_t)b * RR + r0) * RR) + cc;

    #pragma unroll 2
    for (int r = r0; r < r0 + ROWS_PER; r++) {
        const float* arow = &sE[r * RSTRIDE];
        unsigned long long acc0 = 0, acc1 = 0, acc2 = 0, acc3 = 0;
        #pragma unroll
        for (int q = 0; q < 4; q++) {
            const unsigned long long* ap =
                reinterpret_cast<const unsigned long long*>(&arow[8 * q]);
            acc0 = fma2(ap[0], bv[4 * q + 0], acc0);
            acc1 = fma2(ap[1], bv[4 * q + 1], acc1);
            acc2 = fma2(ap[2], bv[4 * q + 2], acc2);
            acc3 = fma2(ap[3], bv[4 * q + 3], acc3);
        }
        float v = sum2(add2(add2(acc0, acc1), add2(acc2, acc3)));
        if (active) {
            int segr = sSeg[r];           // broadcast LDS
            *adjp   = v;
            *intrap = (segr == segc) ? v : 0.0f;
        }
        adjp   += RR;
        intrap += RR;
    }

    // ---- inter-network block means, only split-0 CTAs (one per batch) ----
    // inter[b,s,t] = (sum_{r in s} e_r) . (sum_{p in t} e_p) / (n_s * n_t)
    if (split == 0) {
        // 288 threads == SS*KK exactly: thread (s,d) computes segment sum
        {
            int s  = tid >> 5;            // tid / 32
            int d  = tid & 31;            // tid % 32
            int st = (s == 0) ? 0 : c_ends[s - 1];
            int en = c_ends[s];
            float a = 0.0f;
            for (int rr2 = st; rr2 < en; rr2++) a += sE[rr2 * RSTRIDE + d];
            sSum[tid] = a;
        }
        __syncthreads();
        if (tid < SS * SS) {
            int s = tid / SS, t = tid % SS;
            float a = 0.0f;
            #pragma unroll
            for (int d = 0; d < KK; d++)
                a += sSum[s * KK + d] * sSum[t * KK + d];
            inter[(size_t)b * SS * SS + tid] = a / (c_sizes[s] * c_sizes[t]);
        }
    }
}

extern "C" void kernel_launch(void* const* d_in, const int* in_sizes, int n_in,
                              void* d_out, int out_size)
{
    (void)in_sizes; (void)n_in; (void)out_size;
    const float* E = (const float*)d_in[0];
    float* out = (float*)d_out;

    dim3 grid(NSPLIT, BB);
    size_t smem = (size_t)RR * RSTRIDE * sizeof(float);
    gram_kernel<<<grid, NTHREADS, smem>>>(E, out);
}